// round 8
// baseline (speedup 1.0000x reference)
#include <cuda_runtime.h>
#include <cooperative_groups.h>
#include <cstdint>

namespace cg = cooperative_groups;

#define H     100
#define TSEQ  8192
#define FUT   1024
#define TOT   (TSEQ + FUT)
#define NSLOT 8
#define NTHR  416
#define CLU   4
#define SRV   224        // service warp base (warp 7) in CTA0/CTA2

typedef unsigned long long u64;

// Communication block — identical static smem layout in every cluster CTA.
// h1ring lives in CTA1 (written by CTA0); pring lives in CTA2 (written by CTA1);
// ack1/cy/yv live in CTA0; ack2 lives in CTA1.
struct __align__(16) Comm {
    float h1ring[NSLOT][128];   // 4 KB
    float pring [NSLOT][400];   // 12.8 KB
    int   ch1;                  // in CTA1: h1 produced counter
    int   cp;                   // in CTA2: p produced counter
    int   ack1;                 // in CTA0: h1 consumed counter
    int   ack2;                 // in CTA1: p consumed counter
    int   cy;                   // in CTA0: y produced counter
    float yv;                   // in CTA0: fed-back y value
};

// ---- cluster-scope flag ops on GENERIC addresses ----
static __device__ __forceinline__ int ld_acq(const int* p) {
    int v;
    asm volatile("ld.acquire.cluster.b32 %0, [%1];" : "=r"(v) : "l"(p) : "memory");
    return v;
}
static __device__ __forceinline__ void st_rel(int* p, int v) {
    asm volatile("st.release.cluster.b32 [%0], %1;" :: "l"(p), "r"(v) : "memory");
}
static __device__ __forceinline__ void fence_cluster() {
    asm volatile("fence.acq_rel.cluster;" ::: "memory");
}
static __device__ __forceinline__ void ffma2(u64& a, u64 w, u64 h) {
    asm("fma.rn.f32x2 %0, %1, %2, %3;" : "=l"(a) : "l"(w), "l"(h), "l"(a));
}
static __device__ __forceinline__ float f2lo(u64 a) { return __uint_as_float((unsigned)a); }
static __device__ __forceinline__ float f2hi(u64 a) { return __uint_as_float((unsigned)(a >> 32)); }
static __device__ __forceinline__ float sigm(float x)  { return __fdividef(1.0f, 1.0f + __expf(-x)); }
static __device__ __forceinline__ float tanh_(float x) { return __fdividef(2.0f, 1.0f + __expf(-2.0f * x)) - 1.0f; }

__global__ void __launch_bounds__(NTHR, 1)
lstm_decoder_kernel(
    const float* __restrict__ input,
    const float* __restrict__ enc_h,
    const float* __restrict__ enc_c,
    const float* __restrict__ w_ih1,
    const float* __restrict__ w_hh1,
    const float* __restrict__ b_ih1,
    const float* __restrict__ b_hh1,
    const float* __restrict__ w_ih2,
    const float* __restrict__ w_hh2,
    const float* __restrict__ b_ih2,
    const float* __restrict__ b_hh2,
    const float* __restrict__ w_lin,
    const float* __restrict__ b_lin,
    float* __restrict__ out)
{
    cg::cluster_group cluster = cg::this_cluster();
    const unsigned rk = cluster.block_rank();

    __shared__ Comm cm;
    __shared__ __align__(16) float sx[TSEQ];     // CTA0 only: staged input
    __shared__ __align__(16) float shA[2][128];  // CTA0: h1 dbuf; CTA2: h2 dbuf
    __shared__ float swl[112];                   // CTA2: w_lin
    __shared__ float syp[2][112];                // CTA2: y partials (dbuf)

    const int t = threadIdx.x;
    // pair mapping (CTA0 / CTA2 compute): warp w lanes l; unit u, role = hi/lo half-warp
    const int u    = ((t >> 5) << 4) + (t & 15);   // w*16 + (l&15)
    const int role = (t >> 4) & 1;
    const bool iscomp = (t < SRV);
    const bool act_th = iscomp && (role == 0) && (u < H);

    if (t == 0) { cm.ch1 = 0; cm.cp = 0; cm.ack1 = 0; cm.ack2 = 0; cm.cy = 0; cm.yv = 0.f; }
    cluster.sync();   // flags visible cluster-wide before any remote traffic

    if (rk == 0) {
        // ================= CTA0: layer-1 LSTM (pair layout, 1 barrier/step) =================
        Comm* c1 = (Comm*)cluster.map_shared_rank(&cm, 1);
        u64 W[4][25];
        float bb[4], wik[4];
        float c1s = 0.f;
        if (iscomp) {
            int uc = (u < H) ? u : 0;                         // clamp: valid loads, values unused
#pragma unroll
            for (int g = 0; g < 4; g++) {
                int row = uc + g * 100;
                const u64* wp = (const u64*)(w_hh1 + row * H + role * 50);
#pragma unroll
                for (int j = 0; j < 25; j++) W[g][j] = wp[j];
                bb[g]  = b_ih1[row] + b_hh1[row];
                wik[g] = w_ih1[row];
            }
        }
        for (int i = t; i < TSEQ; i += NTHR) sx[i] = input[i];
        if (act_th) { shA[0][u] = enc_h[u]; c1s = enc_c[u]; }
        __syncthreads();

        for (int step = 0; step < TOT; ++step) {
            const int sel = step & 1;
            if (iscomp) {
                const u64* hp = (const u64*)shA[sel] + role * 25;
                u64 a0 = 0, a1 = 0, a2 = 0, a3 = 0;
#pragma unroll
                for (int j = 0; j < 25; j++) {
                    u64 hv = hp[j];
                    ffma2(a0, W[0][j], hv); ffma2(a1, W[1][j], hv);
                    ffma2(a2, W[2][j], hv); ffma2(a3, W[3][j], hv);
                }
                float g0 = f2lo(a0) + f2hi(a0), g1 = f2lo(a1) + f2hi(a1);
                float g2 = f2lo(a2) + f2hi(a2), g3 = f2lo(a3) + f2hi(a3);
                g0 += __shfl_xor_sync(0xffffffffu, g0, 16);
                g1 += __shfl_xor_sync(0xffffffffu, g1, 16);
                g2 += __shfl_xor_sync(0xffffffffu, g2, 16);
                g3 += __shfl_xor_sync(0xffffffffu, g3, 16);
                if (act_th) {
                    float x = (step < TSEQ) ? sx[step] : cm.yv;
                    g0 = fmaf(x, wik[0], g0 + bb[0]);
                    g1 = fmaf(x, wik[1], g1 + bb[1]);
                    g2 = fmaf(x, wik[2], g2 + bb[2]);
                    g3 = fmaf(x, wik[3], g3 + bb[3]);
                    c1s = sigm(g1) * c1s + sigm(g0) * tanh_(g2);
                    float hh = sigm(g3) * tanh_(c1s);
                    shA[sel ^ 1][u] = hh;
                    c1->h1ring[step & (NSLOT - 1)][u] = hh;   // DSMEM write into CTA1
                }
            } else if (t == SRV) {
                // lookahead: ensure slot (step+1)&7 is free before step+1 writes it
                if (step + 1 >= NSLOT) {
                    while (ld_acq(&cm.ack1) < step + 2 - NSLOT) {}
                }
            }
            __syncthreads();                                  // single barrier (seq)
            if (t == SRV) {
                fence_cluster();
                st_rel(&c1->ch1, step + 1);
                if (step >= TSEQ - 1) {                       // prepare y(step) as next x
                    while (ld_acq(&cm.cy) < step + 1) {}
                }
            }
            if (step >= TSEQ - 1) __syncthreads();            // Bf: yv visible to compute
        }
    } else if (rk == 1) {
        // ================= CTA1: p = W_ih2 @ h1 + b2 (1 row/thread, 1 barrier/step) =================
        Comm* c0 = (Comm*)cluster.map_shared_rank(&cm, 0);
        Comm* c2 = (Comm*)cluster.map_shared_rank(&cm, 2);
        u64 W[50];
        float bb = 0.f;
        if (t < 400) {
            const u64* wp = (const u64*)(w_ih2 + t * H);
#pragma unroll
            for (int j = 0; j < 50; j++) W[j] = wp[j];
            bb = b_ih2[t] + b_hh2[t];
        }
        __syncthreads();

        for (int step = 0; step < TOT; ++step) {
            if (t < 400) {
                while (ld_acq(&cm.ch1) < step + 1) {}
                const u64* hp = (const u64*)cm.h1ring[step & (NSLOT - 1)];
                u64 a0 = 0, a1 = 0;
#pragma unroll
                for (int j = 0; j < 25; j++) {
                    ffma2(a0, W[2 * j],     hp[2 * j]);
                    ffma2(a1, W[2 * j + 1], hp[2 * j + 1]);
                }
                float p = f2lo(a0) + f2hi(a0) + f2lo(a1) + f2hi(a1) + bb;
                c2->pring[step & (NSLOT - 1)][t] = p;         // DSMEM write into CTA2
            } else if (t == 408) {
                if (step + 1 >= NSLOT) {
                    while (ld_acq(&cm.ack2) < step + 2 - NSLOT) {}
                }
            }
            __syncthreads();
            if (t == 400) {
                fence_cluster();
                st_rel(&c2->cp, step + 1);
                st_rel(&c0->ack1, step + 1);
            }
        }
    } else if (rk == 2) {
        // ================= CTA2: layer-2 LSTM + output (pair layout, 1 barrier/step) =================
        Comm* c0 = (Comm*)cluster.map_shared_rank(&cm, 0);
        Comm* c1 = (Comm*)cluster.map_shared_rank(&cm, 1);
        u64 W[4][25];
        float c2s = 0.f;
        if (iscomp) {
            int uc = (u < H) ? u : 0;
#pragma unroll
            for (int g = 0; g < 4; g++) {
                int row = uc + g * 100;
                const u64* wp = (const u64*)(w_hh2 + row * H + role * 50);
#pragma unroll
                for (int j = 0; j < 25; j++) W[g][j] = wp[j];
            }
        }
        if (t < H) swl[t] = w_lin[t];
        if (act_th) shA[0][u] = 0.f;
        const float blin = b_lin[0];
        __syncthreads();

        for (int step = 0; step < TOT; ++step) {
            const int sel = step & 1;
            if (iscomp) {
                while (ld_acq(&cm.cp) < step + 1) {}
                const u64* hp = (const u64*)shA[sel] + role * 25;
                u64 a0 = 0, a1 = 0, a2 = 0, a3 = 0;
#pragma unroll
                for (int j = 0; j < 25; j++) {
                    u64 hv = hp[j];
                    ffma2(a0, W[0][j], hv); ffma2(a1, W[1][j], hv);
                    ffma2(a2, W[2][j], hv); ffma2(a3, W[3][j], hv);
                }
                float g0 = f2lo(a0) + f2hi(a0), g1 = f2lo(a1) + f2hi(a1);
                float g2 = f2lo(a2) + f2hi(a2), g3 = f2lo(a3) + f2hi(a3);
                g0 += __shfl_xor_sync(0xffffffffu, g0, 16);
                g1 += __shfl_xor_sync(0xffffffffu, g1, 16);
                g2 += __shfl_xor_sync(0xffffffffu, g2, 16);
                g3 += __shfl_xor_sync(0xffffffffu, g3, 16);
                if (act_th) {
                    const float* pp = cm.pring[step & (NSLOT - 1)];
                    g0 += pp[u];        g1 += pp[u + 100];
                    g2 += pp[u + 200];  g3 += pp[u + 300];
                    c2s = sigm(g1) * c2s + sigm(g0) * tanh_(g2);
                    float hh = sigm(g3) * tanh_(c2s);
                    shA[sel ^ 1][u] = hh;
                    syp[sel][u] = hh * swl[u];
                }
            }
            __syncthreads();
            if (t == 300) {                                   // idle warp: p-ring ack
                fence_cluster();
                st_rel(&c1->ack2, step + 1);
            }
            if (t >= SRV && t < SRV + 32) {                   // service warp: y reduction
                int sl = t - SRV;
                const float* sp = syp[sel];
                float v = sp[sl];                             // sl < 32 < 100 always valid
                v += sp[sl + 32];
                v += (sl + 64 < H) ? sp[sl + 64] : 0.f;
                v += (sl + 96 < H) ? sp[sl + 96] : 0.f;
                v += __shfl_xor_sync(0xffffffffu, v, 16);
                v += __shfl_xor_sync(0xffffffffu, v, 8);
                v += __shfl_xor_sync(0xffffffffu, v, 4);
                v += __shfl_xor_sync(0xffffffffu, v, 2);
                v += __shfl_xor_sync(0xffffffffu, v, 1);
                if (sl == 0) {
                    float y = v + blin;
                    out[step] = y;
                    if (step >= TSEQ - 1) {
                        c0->yv = y;                           // own store, ordered by release below
                        st_rel(&c0->cy, step + 1);
                    }
                }
            }
        }
    }
    // rk == 3: idle spacer CTA — participates in the cluster barriers only.

    cluster.sync();   // lifetime guard: no CTA exits while peers may still write its SMEM
}

extern "C" void kernel_launch(void* const* d_in, const int* in_sizes, int n_in,
                              void* d_out, int out_size) {
    (void)in_sizes; (void)n_in; (void)out_size;
    const float* input = (const float*)d_in[0];
    const float* eh    = (const float*)d_in[1];
    const float* ec    = (const float*)d_in[2];
    const float* wih1  = (const float*)d_in[3];
    const float* whh1  = (const float*)d_in[4];
    const float* bih1  = (const float*)d_in[5];
    const float* bhh1  = (const float*)d_in[6];
    const float* wih2  = (const float*)d_in[7];
    const float* whh2  = (const float*)d_in[8];
    const float* bih2  = (const float*)d_in[9];
    const float* bhh2  = (const float*)d_in[10];
    const float* wlin  = (const float*)d_in[11];
    const float* blin  = (const float*)d_in[12];
    float* out = (float*)d_out;

    cudaLaunchConfig_t cfg = {};
    cfg.gridDim  = dim3(CLU, 1, 1);
    cfg.blockDim = dim3(NTHR, 1, 1);
    cfg.dynamicSmemBytes = 0;
    cudaLaunchAttribute attrs[1];
    attrs[0].id = cudaLaunchAttributeClusterDimension;
    attrs[0].val.clusterDim.x = CLU;
    attrs[0].val.clusterDim.y = 1;
    attrs[0].val.clusterDim.z = 1;
    cfg.attrs = attrs;
    cfg.numAttrs = 1;

    cudaLaunchKernelEx(&cfg, lstm_decoder_kernel,
                       input, eh, ec, wih1, whh1, bih1, bhh1,
                       wih2, whh2, bih2, bhh2, wlin, blin, out);
}

// round 9
// speedup vs baseline: 1.3758x; 1.3758x over previous
#include <cuda_runtime.h>
#include <cooperative_groups.h>
#include <cstdint>

namespace cg = cooperative_groups;

#define H     100
#define G4    400
#define TSEQ  8192
#define FUT   1024
#define TOT   (TSEQ + FUT)
#define NSLOT 8
#define NTHR  480
#define SIGA  416     // warp 13 lane 0: even-step signaler
#define SIGB  448     // warp 14 lane 0: odd-step signaler (CTA0/CTA1); y-warp base in CTA2

typedef unsigned long long u64;

// Communication block — identical static smem layout in every cluster CTA.
// h1ring lives in CTA1 (written by CTA0); pring lives in CTA2 (written by CTA1);
// ack1/cy/yv live in CTA0; ack2 lives in CTA1.
struct __align__(16) Comm {
    float h1ring[NSLOT][128];   // 4 KB
    float pring [NSLOT][400];   // 12.8 KB
    int   ch1;                  // in CTA1: h1 produced counter
    int   cp;                   // in CTA2: p produced counter
    int   ack1;                 // in CTA0: h1 consumed counter
    int   ack2;                 // in CTA1: p consumed counter
    int   cy;                   // in CTA0: y produced counter
    float yv;                   // in CTA0: fed-back y value
};

// ---- shared-window address helpers ----
static __device__ __forceinline__ uint32_t sm2u(const void* p) {
    uint32_t a;
    asm("{ .reg .u64 t; cvta.to.shared.u64 t, %1; cvt.u32.u64 %0, t; }" : "=r"(a) : "l"(p));
    return a;
}
static __device__ __forceinline__ uint32_t mapa_(uint32_t a, uint32_t rank) {
    uint32_t o; asm("mapa.shared::cluster.u32 %0, %1, %2;" : "=r"(o) : "r"(a), "r"(rank));
    return o;
}
// local smem poll: LDS-speed acquire
static __device__ __forceinline__ int ld_acq_sh(uint32_t la) {
    int v; asm volatile("ld.acquire.cluster.shared::cta.b32 %0, [%1];" : "=r"(v) : "r"(la) : "memory");
    return v;
}
// remote flag signal: DSMEM release store
static __device__ __forceinline__ void st_rel_sh(uint32_t ra, int v) {
    asm volatile("st.release.cluster.shared::cluster.b32 [%0], %1;" :: "r"(ra), "r"(v) : "memory");
}
// remote data store: weak DSMEM store
static __device__ __forceinline__ void st_f32_sh(uint32_t ra, float v) {
    asm volatile("st.shared::cluster.f32 [%0], %1;" :: "r"(ra), "f"(v) : "memory");
}
static __device__ __forceinline__ void fence_cluster() {
    asm volatile("fence.acq_rel.cluster;" ::: "memory");
}
static __device__ __forceinline__ void ffma2(u64& a, u64 w, u64 h) {
    asm("fma.rn.f32x2 %0, %1, %2, %3;" : "=l"(a) : "l"(w), "l"(h), "l"(a));
}
static __device__ __forceinline__ float f2lo(u64 a) { return __uint_as_float((unsigned)a); }
static __device__ __forceinline__ float f2hi(u64 a) { return __uint_as_float((unsigned)(a >> 32)); }
static __device__ __forceinline__ float sigm(float x)  { return __fdividef(1.0f, 1.0f + __expf(-x)); }
static __device__ __forceinline__ float tanh_(float x) { return __fdividef(2.0f, 1.0f + __expf(-2.0f * x)) - 1.0f; }

// 100-wide dot: 25 LDS.128 + 50 packed f32x2 FMAs against register weights.
static __device__ __forceinline__ float dot100(const u64* W, const float* sh) {
    const ulonglong2* h = (const ulonglong2*)sh;
    u64 a0 = 0ull, a1 = 0ull;
#pragma unroll
    for (int j = 0; j < 25; j++) {
        ulonglong2 hv = h[j];
        ffma2(a0, W[2 * j],     hv.x);
        ffma2(a1, W[2 * j + 1], hv.y);
    }
    return f2lo(a0) + f2hi(a0) + f2lo(a1) + f2hi(a1);
}

__global__ void __launch_bounds__(NTHR, 1)
lstm_decoder_kernel(
    const float* __restrict__ input,
    const float* __restrict__ enc_h,
    const float* __restrict__ enc_c,
    const float* __restrict__ w_ih1,
    const float* __restrict__ w_hh1,
    const float* __restrict__ b_ih1,
    const float* __restrict__ b_hh1,
    const float* __restrict__ w_ih2,
    const float* __restrict__ w_hh2,
    const float* __restrict__ b_ih2,
    const float* __restrict__ b_hh2,
    const float* __restrict__ w_lin,
    const float* __restrict__ b_lin,
    float* __restrict__ out)
{
    cg::cluster_group cluster = cg::this_cluster();
    const unsigned rk = cluster.block_rank();

    __shared__ Comm cm;
    __shared__ __align__(16) float sx[TSEQ];   // CTA0 only: staged input
    __shared__ __align__(16) float shA[128];   // CTA0: h1 state; CTA2: h2 state
    __shared__ float sg[400];
    __shared__ float swl[112];
    __shared__ float syp[2][112];

    const int t = threadIdx.x;

    // local flag addresses
    const uint32_t a_ch1  = sm2u(&cm.ch1);
    const uint32_t a_cp   = sm2u(&cm.cp);
    const uint32_t a_ack1 = sm2u(&cm.ack1);
    const uint32_t a_ack2 = sm2u(&cm.ack2);
    const uint32_t a_cy   = sm2u(&cm.cy);

    if (t == 0) { cm.ch1 = 0; cm.cp = 0; cm.ack1 = 0; cm.ack2 = 0; cm.cy = 0; cm.yv = 0.f; }
    cluster.sync();   // flags visible cluster-wide before any remote traffic

    if (rk == 0) {
        // ======================= CTA0: layer-1 LSTM =======================
        const uint32_t r_h1  = mapa_(sm2u(cm.h1ring), 1);   // data ring in CTA1
        const uint32_t r_ch1 = mapa_(a_ch1, 1);
        u64 Wr[50];
        float wi = 0.f, bb = 0.f, c1s = 0.f;
        if (t < G4) {
            const u64* wp = (const u64*)(w_hh1 + t * H);
#pragma unroll
            for (int j = 0; j < 50; j++) Wr[j] = wp[j];
            wi = w_ih1[t];
            bb = b_ih1[t] + b_hh1[t];
        }
        for (int i = t; i < TSEQ; i += NTHR) sx[i] = input[i];
        if (t < H) { shA[t] = enc_h[t]; c1s = enc_c[t]; }
        __syncthreads();

        for (int step = 0; step < TOT; ++step) {
            if (t < G4) {
                if (step >= NSLOT) {
                    while (ld_acq_sh(a_ack1) < step - (NSLOT - 1)) {}
                }
                float x;
                if (step < TSEQ) x = sx[step];
                else {
                    while (ld_acq_sh(a_cy) < step) {}
                    x = cm.yv;
                }
                float a = dot100(Wr, shA);
                sg[t] = fmaf(x, wi, a + bb);
            }
            __syncthreads();                                  // B1
            if (t < H) {
                float ig = sg[t], fg = sg[t + 100], gg = sg[t + 200], og = sg[t + 300];
                c1s = sigm(fg) * c1s + sigm(ig) * tanh_(gg);
                float hh = sigm(og) * tanh_(c1s);
                shA[t] = hh;
                st_f32_sh(r_h1 + (((step & (NSLOT - 1)) << 7) + t) * 4, hh);
            }
            __syncthreads();                                  // B2
            // alternating signal warps: fence has a full step of slack
            if (((step & 1) == 0 && t == SIGA) || ((step & 1) == 1 && t == SIGB)) {
                fence_cluster();
                st_rel_sh(r_ch1, step + 1);
            }
        }
    } else if (rk == 1) {
        // ======================= CTA1: p = W_ih2 @ h1 + b2 =======================
        const uint32_t r_p    = mapa_(sm2u(cm.pring), 2);    // data ring in CTA2
        const uint32_t r_cp   = mapa_(a_cp, 2);
        const uint32_t r_ack1 = mapa_(a_ack1, 0);
        u64 Wr[50];
        float bb = 0.f;
        if (t < G4) {
            const u64* wp = (const u64*)(w_ih2 + t * H);
#pragma unroll
            for (int j = 0; j < 50; j++) Wr[j] = wp[j];
            bb = b_ih2[t] + b_hh2[t];
        }
        __syncthreads();

        for (int step = 0; step < TOT; ++step) {
            if (t < G4) {
                while (ld_acq_sh(a_ch1) < step + 1) {}
                if (step >= NSLOT) {
                    while (ld_acq_sh(a_ack2) < step - (NSLOT - 1)) {}
                }
                float p = dot100(Wr, cm.h1ring[step & (NSLOT - 1)]) + bb;
                st_f32_sh(r_p + ((step & (NSLOT - 1)) * 400 + t) * 4, p);
            }
            __syncthreads();                                  // single barrier/step
            if (((step & 1) == 0 && t == SIGA) || ((step & 1) == 1 && t == SIGB)) {
                fence_cluster();
                st_rel_sh(r_cp, step + 1);
                if (step & 1) st_rel_sh(r_ack1, step + 1);    // 2-step cadence ack
            }
        }
    } else if (rk == 2) {
        // ======================= CTA2: layer-2 recurrence + output =======================
        const uint32_t r_ack2 = mapa_(a_ack2, 1);
        const uint32_t r_cy   = mapa_(a_cy, 0);
        const uint32_t r_yv   = mapa_(sm2u(&cm.yv), 0);
        u64 Wr[50];
        float c2s = 0.f;
        if (t < G4) {
            const u64* wp = (const u64*)(w_hh2 + t * H);
#pragma unroll
            for (int j = 0; j < 50; j++) Wr[j] = wp[j];
        }
        if (t < H) { shA[t] = 0.f; swl[t] = w_lin[t]; }
        const float blin = b_lin[0];
        __syncthreads();

        for (int step = 0; step < TOT; ++step) {
            const int sel = step & 1;
            if (t < G4) {
                while (ld_acq_sh(a_cp) < step + 1) {}
                float q = dot100(Wr, shA);                    // W_hh2 @ h2(step-1)
                sg[t] = q + cm.pring[step & (NSLOT - 1)][t];
            }
            __syncthreads();                                  // B1 (p consumed)
            if (t < H) {
                float ig = sg[t], fg = sg[t + 100], gg = sg[t + 200], og = sg[t + 300];
                c2s = sigm(fg) * c2s + sigm(ig) * tanh_(gg);
                float hh = sigm(og) * tanh_(c2s);
                shA[t] = hh;
                syp[sel][t] = hh * swl[t];
            }
            __syncthreads();                                  // B2
            if (t == SIGA && (step & 1)) {                    // 2-step cadence ack
                fence_cluster();
                st_rel_sh(r_ack2, step + 1);
            }
            if (t >= SIGB) {                                  // warp 14: y reduction
                int sl = t - SIGB;
                const float* sp = syp[sel];
                float v = 0.f;
                if (sl < 25) {
                    int b4 = 4 * sl;
                    v = sp[b4] + sp[b4 + 1] + sp[b4 + 2] + sp[b4 + 3];
                }
                v += __shfl_xor_sync(0xffffffffu, v, 16);
                v += __shfl_xor_sync(0xffffffffu, v, 8);
                v += __shfl_xor_sync(0xffffffffu, v, 4);
                v += __shfl_xor_sync(0xffffffffu, v, 2);
                v += __shfl_xor_sync(0xffffffffu, v, 1);
                if (sl == 0) {
                    float y = v + blin;
                    out[step] = y;
                    if (step >= TSEQ - 1) {
                        st_f32_sh(r_yv, y);                   // own store, ordered by release below
                        st_rel_sh(r_cy, step + 1);
                    }
                }
            }
        }
    }
    // rk == 3: idle spacer CTA — participates in the cluster barriers only.

    cluster.sync();   // lifetime guard: no CTA exits while peers may still write its SMEM
}

extern "C" void kernel_launch(void* const* d_in, const int* in_sizes, int n_in,
                              void* d_out, int out_size) {
    (void)in_sizes; (void)n_in; (void)out_size;
    const float* input = (const float*)d_in[0];
    const float* eh    = (const float*)d_in[1];
    const float* ec    = (const float*)d_in[2];
    const float* wih1  = (const float*)d_in[3];
    const float* whh1  = (const float*)d_in[4];
    const float* bih1  = (const float*)d_in[5];
    const float* bhh1  = (const float*)d_in[6];
    const float* wih2  = (const float*)d_in[7];
    const float* whh2  = (const float*)d_in[8];
    const float* bih2  = (const float*)d_in[9];
    const float* bhh2  = (const float*)d_in[10];
    const float* wlin  = (const float*)d_in[11];
    const float* blin  = (const float*)d_in[12];
    float* out = (float*)d_out;

    cudaLaunchConfig_t cfg = {};
    cfg.gridDim  = dim3(4, 1, 1);
    cfg.blockDim = dim3(NTHR, 1, 1);
    cfg.dynamicSmemBytes = 0;
    cudaLaunchAttribute attrs[1];
    attrs[0].id = cudaLaunchAttributeClusterDimension;
    attrs[0].val.clusterDim.x = 4;
    attrs[0].val.clusterDim.y = 1;
    attrs[0].val.clusterDim.z = 1;
    cfg.attrs = attrs;
    cfg.numAttrs = 1;

    cudaLaunchKernelEx(&cfg, lstm_decoder_kernel,
                       input, eh, ec, wih1, whh1, bih1, bhh1,
                       wih2, whh2, bih2, bhh2, wlin, blin, out);
}

// round 10
// speedup vs baseline: 1.5864x; 1.1530x over previous
#include <cuda_runtime.h>
#include <cooperative_groups.h>
#include <cstdint>

namespace cg = cooperative_groups;

#define H     100
#define G4    400
#define TSEQ  8192
#define FUT   1024
#define TOT   (TSEQ + FUT)
#define NSLOT 8
#define NTHR  480
#define SIGA  416     // warp 13 lane 0: signaler
#define SIGB  448     // warp 14: y-reduction warp (CTA2)

typedef unsigned long long u64;

// Communication block — identical static smem layout in every cluster CTA.
// h1ring+fullh live in CTA1; pring+fullp live in CTA2; ybuf+fully+freeh live in CTA0; freep in CTA1.
struct __align__(16) Comm {
    float h1ring[NSLOT][128];   // in CTA1, written by CTA0 via st.async
    float pring [NSLOT][400];   // in CTA2, written by CTA1 via st.async
    float ybuf[2];              // in CTA0, written by CTA2 via st.async
    u64   fullh[NSLOT];         // in CTA1: h1 slot data-arrived
    u64   freeh[NSLOT];         // in CTA0: h1 slot consumed
    u64   fullp[NSLOT];         // in CTA2: p slot data-arrived
    u64   freep[NSLOT];         // in CTA1: p slot consumed
    u64   fully[2];             // in CTA0: y arrived
};

// ---- address helpers ----
static __device__ __forceinline__ uint32_t sm2u(const void* p) {
    uint32_t a;
    asm("{ .reg .u64 t; cvta.to.shared.u64 t, %1; cvt.u32.u64 %0, t; }" : "=r"(a) : "l"(p));
    return a;
}
static __device__ __forceinline__ uint32_t mapa_(uint32_t a, uint32_t rank) {
    uint32_t o; asm("mapa.shared::cluster.u32 %0, %1, %2;" : "=r"(o) : "r"(a), "r"(rank));
    return o;
}
// ---- mbarrier ops ----
static __device__ __forceinline__ void mbar_init(uint32_t a, uint32_t cnt) {
    asm volatile("mbarrier.init.shared.b64 [%0], %1;" :: "r"(a), "r"(cnt) : "memory");
}
static __device__ __forceinline__ void mbar_wait(uint32_t a, uint32_t parity) {
    asm volatile(
        "{\n\t.reg .pred P;\n\t"
        "WL%=:\n\t"
        "mbarrier.try_wait.parity.acquire.cluster.shared::cta.b64 P, [%0], %1, 0x989680;\n\t"
        "@P bra.uni WD%=;\n\t"
        "bra.uni WL%=;\n\t"
        "WD%=:\n\t}"
        :: "r"(a), "r"(parity) : "memory");
}
// remote producer signal: one arrival carrying the expected byte count
static __device__ __forceinline__ void arrive_tx_remote(uint32_t ra, uint32_t tx) {
    asm volatile("mbarrier.arrive.expect_tx.shared::cluster.b64 _, [%0], %1;"
                 :: "r"(ra), "r"(tx) : "memory");
}
// remote consumer ack: plain arrival
static __device__ __forceinline__ void arrive_remote(uint32_t ra) {
    asm volatile("mbarrier.arrive.shared::cluster.b64 _, [%0];" :: "r"(ra) : "memory");
}
// async DSMEM data store, tx-tracked by the co-located remote mbarrier
static __device__ __forceinline__ void st_async_f32(uint32_t ra, float v, uint32_t rmbar) {
    asm volatile("st.async.shared::cluster.mbarrier::complete_tx::bytes.b32 [%0], %1, [%2];"
                 :: "r"(ra), "r"(__float_as_uint(v)), "r"(rmbar) : "memory");
}
static __device__ __forceinline__ void ffma2(u64& a, u64 w, u64 h) {
    asm("fma.rn.f32x2 %0, %1, %2, %3;" : "=l"(a) : "l"(w), "l"(h), "l"(a));
}
static __device__ __forceinline__ float f2lo(u64 a) { return __uint_as_float((unsigned)a); }
static __device__ __forceinline__ float f2hi(u64 a) { return __uint_as_float((unsigned)(a >> 32)); }
static __device__ __forceinline__ float sigm(float x)  { return __fdividef(1.0f, 1.0f + __expf(-x)); }
static __device__ __forceinline__ float tanh_(float x) { return __fdividef(2.0f, 1.0f + __expf(-2.0f * x)) - 1.0f; }

// 100-wide dot: 25 LDS.128 + 50 packed f32x2 FMAs against register weights.
static __device__ __forceinline__ float dot100(const u64* W, const float* sh) {
    const ulonglong2* h = (const ulonglong2*)sh;
    u64 a0 = 0ull, a1 = 0ull;
#pragma unroll
    for (int j = 0; j < 25; j++) {
        ulonglong2 hv = h[j];
        ffma2(a0, W[2 * j],     hv.x);
        ffma2(a1, W[2 * j + 1], hv.y);
    }
    return f2lo(a0) + f2hi(a0) + f2lo(a1) + f2hi(a1);
}

__global__ void __launch_bounds__(NTHR, 1)
lstm_decoder_kernel(
    const float* __restrict__ input,
    const float* __restrict__ enc_h,
    const float* __restrict__ enc_c,
    const float* __restrict__ w_ih1,
    const float* __restrict__ w_hh1,
    const float* __restrict__ b_ih1,
    const float* __restrict__ b_hh1,
    const float* __restrict__ w_ih2,
    const float* __restrict__ w_hh2,
    const float* __restrict__ b_ih2,
    const float* __restrict__ b_hh2,
    const float* __restrict__ w_lin,
    const float* __restrict__ b_lin,
    float* __restrict__ out)
{
    cg::cluster_group cluster = cg::this_cluster();
    const unsigned rk = cluster.block_rank();

    __shared__ Comm cm;
    __shared__ __align__(16) float sx[TSEQ];   // CTA0 only: staged input
    __shared__ __align__(16) float shA[128];   // CTA0: h1 state; CTA2: h2 state
    __shared__ float sg[400];
    __shared__ float swl[112];
    __shared__ float syp[2][112];

    const int t = threadIdx.x;

    // local mbar base addresses
    const uint32_t a_fullh = sm2u(cm.fullh);
    const uint32_t a_freeh = sm2u(cm.freeh);
    const uint32_t a_fullp = sm2u(cm.fullp);
    const uint32_t a_freep = sm2u(cm.freep);
    const uint32_t a_fully = sm2u(cm.fully);

    if (t == 0) {
        for (int s = 0; s < NSLOT; s++) {
            mbar_init(a_fullh + s * 8, 1);
            mbar_init(a_freeh + s * 8, 1);
            mbar_init(a_fullp + s * 8, 1);
            mbar_init(a_freep + s * 8, 1);
        }
        mbar_init(a_fully, 1);
        mbar_init(a_fully + 8, 1);
    }
    __syncthreads();
    cluster.sync();   // all mbarriers initialized cluster-wide before any async traffic

    if (rk == 0) {
        // ======================= CTA0: layer-1 LSTM =======================
        const uint32_t r_h1    = mapa_(sm2u(cm.h1ring), 1);
        const uint32_t r_fullh = mapa_(a_fullh, 1);
        u64 Wr[50];
        float wi = 0.f, bb = 0.f, c1s = 0.f;
        if (t < G4) {
            const u64* wp = (const u64*)(w_hh1 + t * H);
#pragma unroll
            for (int j = 0; j < 50; j++) Wr[j] = wp[j];
            wi = w_ih1[t];
            bb = b_ih1[t] + b_hh1[t];
        }
        for (int i = t; i < TSEQ; i += NTHR) sx[i] = input[i];
        if (t < H) { shA[t] = enc_h[t]; c1s = enc_c[t]; }
        __syncthreads();

        for (int step = 0; step < TOT; ++step) {
            const int slot = step & (NSLOT - 1);
            if (t < G4) {
                float x;
                if (step < TSEQ) x = sx[step];
                else {
                    const int fi = step - TSEQ;                 // y(step-1) = production index fi
                    mbar_wait(a_fully + (fi & 1) * 8, (fi >> 1) & 1);
                    x = cm.ybuf[fi & 1];
                }
                float a = dot100(Wr, shA);
                sg[t] = fmaf(x, wi, a + bb);
            }
            __syncthreads();                                    // B1
            if (t < H) {
                float ig = sg[t], fg = sg[t + 100], gg = sg[t + 200], og = sg[t + 300];
                c1s = sigm(fg) * c1s + sigm(ig) * tanh_(gg);
                float hh = sigm(og) * tanh_(c1s);
                shA[t] = hh;
                if (step >= NSLOT)                              // slot reuse backpressure
                    mbar_wait(a_freeh + slot * 8, ((step >> 3) + 1) & 1);
                st_async_f32(r_h1 + (slot * 128 + t) * 4, hh, r_fullh + slot * 8);
            }
            __syncthreads();                                    // B2
            if (t == SIGA) arrive_tx_remote(r_fullh + slot * 8, 400);   // 100 floats expected
        }
    } else if (rk == 1) {
        // ======================= CTA1: p = W_ih2 @ h1 + b2 =======================
        const uint32_t r_p     = mapa_(sm2u(cm.pring), 2);
        const uint32_t r_fullp = mapa_(a_fullp, 2);
        const uint32_t r_freeh = mapa_(a_freeh, 0);
        u64 Wr[50];
        float bb = 0.f;
        if (t < G4) {
            const u64* wp = (const u64*)(w_ih2 + t * H);
#pragma unroll
            for (int j = 0; j < 50; j++) Wr[j] = wp[j];
            bb = b_ih2[t] + b_hh2[t];
        }
        __syncthreads();

        for (int step = 0; step < TOT; ++step) {
            const int slot = step & (NSLOT - 1);
            if (t < G4) {
                mbar_wait(a_fullh + slot * 8, (step >> 3) & 1); // h1(step) landed
                float p = dot100(Wr, cm.h1ring[slot]) + bb;
                if (step >= NSLOT)
                    mbar_wait(a_freep + slot * 8, ((step >> 3) + 1) & 1);
                st_async_f32(r_p + (slot * 400 + t) * 4, p, r_fullp + slot * 8);
            }
            __syncthreads();                                    // single barrier/step
            if (t == SIGA) {
                arrive_tx_remote(r_fullp + slot * 8, 1600);     // 400 floats expected
                if (step < TOT - NSLOT)                         // no consumer near exit
                    arrive_remote(r_freeh + slot * 8);          // h1(step) consumed
            }
        }
    } else if (rk == 2) {
        // ======================= CTA2: layer-2 recurrence + output =======================
        const uint32_t r_freep = mapa_(a_freep, 1);
        const uint32_t r_ybuf  = mapa_(sm2u(cm.ybuf), 0);
        const uint32_t r_fully = mapa_(a_fully, 0);
        u64 Wr[50];
        float c2s = 0.f;
        if (t < G4) {
            const u64* wp = (const u64*)(w_hh2 + t * H);
#pragma unroll
            for (int j = 0; j < 50; j++) Wr[j] = wp[j];
        }
        if (t < H) { shA[t] = 0.f; swl[t] = w_lin[t]; }
        const float blin = b_lin[0];
        __syncthreads();

        for (int step = 0; step < TOT; ++step) {
            const int slot = step & (NSLOT - 1);
            const int sel  = step & 1;
            if (t < G4) {
                mbar_wait(a_fullp + slot * 8, (step >> 3) & 1); // p(step) landed
                float q = dot100(Wr, shA);                      // W_hh2 @ h2(step-1)
                sg[t] = q + cm.pring[slot][t];
            }
            __syncthreads();                                    // B1 (p consumed)
            if (t == SIGA && step < TOT - NSLOT)
                arrive_remote(r_freep + slot * 8);
            if (t < H) {
                float ig = sg[t], fg = sg[t + 100], gg = sg[t + 200], og = sg[t + 300];
                c2s = sigm(fg) * c2s + sigm(ig) * tanh_(gg);
                float hh = sigm(og) * tanh_(c2s);
                shA[t] = hh;
                syp[sel][t] = hh * swl[t];
            }
            __syncthreads();                                    // B2
            if (t >= SIGB) {                                    // warp 14: y reduction
                int sl = t - SIGB;
                const float* sp = syp[sel];
                float v = 0.f;
                if (sl < 25) {
                    int b4 = 4 * sl;
                    v = sp[b4] + sp[b4 + 1] + sp[b4 + 2] + sp[b4 + 3];
                }
                v += __shfl_xor_sync(0xffffffffu, v, 16);
                v += __shfl_xor_sync(0xffffffffu, v, 8);
                v += __shfl_xor_sync(0xffffffffu, v, 4);
                v += __shfl_xor_sync(0xffffffffu, v, 2);
                v += __shfl_xor_sync(0xffffffffu, v, 1);
                if (sl == 0) {
                    float y = v + blin;
                    out[step] = y;
                    // feed back y(step) for CTA0's step+1; skip the final one (never consumed,
                    // avoids an in-flight DSMEM store at kernel exit)
                    if (step >= TSEQ - 1 && step < TOT - 1) {
                        const int fi = step - (TSEQ - 1);
                        st_async_f32(r_ybuf + (fi & 1) * 4, y, r_fully + (fi & 1) * 8);
                        arrive_tx_remote(r_fully + (fi & 1) * 8, 4);
                    }
                }
            }
        }
    }
    // rk == 3: idle spacer CTA — participates in the cluster barriers only.

    cluster.sync();   // lifetime guard: no CTA exits while peers may still write its SMEM
}

extern "C" void kernel_launch(void* const* d_in, const int* in_sizes, int n_in,
                              void* d_out, int out_size) {
    (void)in_sizes; (void)n_in; (void)out_size;
    const float* input = (const float*)d_in[0];
    const float* eh    = (const float*)d_in[1];
    const float* ec    = (const float*)d_in[2];
    const float* wih1  = (const float*)d_in[3];
    const float* whh1  = (const float*)d_in[4];
    const float* bih1  = (const float*)d_in[5];
    const float* bhh1  = (const float*)d_in[6];
    const float* wih2  = (const float*)d_in[7];
    const float* whh2  = (const float*)d_in[8];
    const float* bih2  = (const float*)d_in[9];
    const float* bhh2  = (const float*)d_in[10];
    const float* wlin  = (const float*)d_in[11];
    const float* blin  = (const float*)d_in[12];
    float* out = (float*)d_out;

    cudaLaunchConfig_t cfg = {};
    cfg.gridDim  = dim3(4, 1, 1);
    cfg.blockDim = dim3(NTHR, 1, 1);
    cfg.dynamicSmemBytes = 0;
    cudaLaunchAttribute attrs[1];
    attrs[0].id = cudaLaunchAttributeClusterDimension;
    attrs[0].val.clusterDim.x = 4;
    attrs[0].val.clusterDim.y = 1;
    attrs[0].val.clusterDim.z = 1;
    cfg.attrs = attrs;
    cfg.numAttrs = 1;

    cudaLaunchKernelEx(&cfg, lstm_decoder_kernel,
                       input, eh, ec, wih1, whh1, bih1, bhh1,
                       wih2, whh2, bih2, bhh2, wlin, blin, out);
}